// round 17
// baseline (speedup 1.0000x reference)
#include <cuda_runtime.h>
#include <cuda_fp16.h>
#include <cstdint>
#include <math.h>

#define B_    2
#define L_    2048
#define DIM_  1024
#define NH    16
#define NKV   4
#define HD    64
#define NTOK  (B_*L_)       // 4096

// ------------------------- scratch (__device__, no mallocs) -----------------
__device__ __align__(16) __half g_qh [NTOK*DIM_];  // Q normed+roped+scaled(1/8), fp16
__device__ __align__(16) __half g_kvh[NTOK*512];   // K roped (0..255) | V (256..511), fp16
__device__ __align__(16) __half g_xh [NTOK*DIM_];  // x, fp16
__device__ __align__(16) __half g_ao [NTOK*DIM_];  // attention out, fp16

__device__ __align__(16) __half g_wt  [1536*DIM_]; // [n][k] fused wq|wk|wv, fp16
__device__ __align__(16) __half g_wot [DIM_*DIM_]; // [n][k] wo, fp16

// ------------------------- helpers ------------------------------------------
__device__ __forceinline__ uint32_t smem_u32(const void* p) {
    uint32_t a;
    asm("{ .reg .u64 t; cvta.to.shared.u64 t, %1; cvt.u32.u64 %0, t; }"
        : "=r"(a) : "l"(p));
    return a;
}
__device__ __forceinline__ void ldm4(uint32_t f[4], uint32_t addr) {
    asm volatile("ldmatrix.sync.aligned.m8n8.x4.shared.b16 {%0,%1,%2,%3}, [%4];"
                 : "=r"(f[0]), "=r"(f[1]), "=r"(f[2]), "=r"(f[3]) : "r"(addr));
}
__device__ __forceinline__ void ldm4t(uint32_t f[4], uint32_t addr) {
    asm volatile("ldmatrix.sync.aligned.m8n8.x4.trans.shared.b16 {%0,%1,%2,%3}, [%4];"
                 : "=r"(f[0]), "=r"(f[1]), "=r"(f[2]), "=r"(f[3]) : "r"(addr));
}
__device__ __forceinline__ void mma16816(float c[4], const uint32_t a[4],
                                         uint32_t b0, uint32_t b1) {
    asm volatile("mma.sync.aligned.m16n8k16.row.col.f32.f16.f16.f32 "
                 "{%0,%1,%2,%3},{%4,%5,%6,%7},{%8,%9},{%0,%1,%2,%3};"
                 : "+f"(c[0]), "+f"(c[1]), "+f"(c[2]), "+f"(c[3])
                 : "r"(a[0]), "r"(a[1]), "r"(a[2]), "r"(a[3]), "r"(b0), "r"(b1));
}
__device__ __forceinline__ uint32_t pack2h(__half a, __half b) {
    return (uint32_t)__half_as_ushort(a) |
           ((uint32_t)__half_as_ushort(b) << 16);
}
__device__ __forceinline__ void cp16(uint32_t saddr, const void* gptr) {
    asm volatile("cp.async.cg.shared.global [%0], [%1], 16;"
                 :: "r"(saddr), "l"(gptr));
}
#define CP_COMMIT() asm volatile("cp.async.commit_group;" ::: "memory")
#define CP_WAIT(n)  asm volatile("cp.async.wait_group %0;" :: "n"(n) : "memory")

#define PITCH     40
#define TILE_H    (128*PITCH)
#define TILE_BY   (TILE_H*2)
#define NKB       (DIM_/32)
#define BUF1_BY   (2*TILE_BY)          // A, B
#define GSMEM1    (3*BUF1_BY)

// ---------------------------------------------------------------------------
// Shared GEMM mainloop body (1-term fp16, cp.async 3-stage) -> acc
// ---------------------------------------------------------------------------
struct GemmCtx {
    float acc[2][8][4];
    int wm, wn, m0, n0, lane;
};

__device__ __forceinline__ void gemm_mainloop(GemmCtx& g, __half* sm,
                                              const __half* __restrict__ A_,
                                              const __half* __restrict__ B_arr) {
    const int tid  = threadIdx.x;
    const int lane = tid & 31;
    const int wm = g.wm, wn = g.wn, m0 = g.m0, n0 = g.n0;
    const uint32_t smb = smem_u32(sm);

    uint32_t aoff[2], boff[4];
    #pragma unroll
    for (int mt = 0; mt < 2; mt++)
        aoff[mt] = ((wm + mt * 16 + (lane & 15)) * PITCH + ((lane >> 4) << 3)) * 2;
    #pragma unroll
    for (int pr = 0; pr < 4; pr++)
        boff[pr] = ((wn + pr * 16 + (lane & 7) + ((lane >> 4) & 1) * 8) * PITCH
                    + (((lane >> 3) & 1) << 3)) * 2;

    #pragma unroll
    for (int i = 0; i < 2; i++)
        #pragma unroll
        for (int j = 0; j < 8; j++)
            #pragma unroll
            for (int r = 0; r < 4; r++) g.acc[i][j][r] = 0.0f;

    const int r0  = (tid * 2)     >> 2, c80 = ((tid * 2)     & 3) << 3;
    const int r1  = (tid * 2 + 1) >> 2, c81 = ((tid * 2 + 1) & 3) << 3;
    const uint32_t so0 = (r0 * PITCH + c80) * 2;
    const uint32_t so1 = (r1 * PITCH + c81) * 2;

    auto stage = [&](int kb, int buf) {
        const int k0 = kb << 5;
        const uint32_t sb = smb + buf * BUF1_BY;
        cp16(sb + so0,           A_    + (size_t)(m0 + r0) * DIM_ + k0 + c80);
        cp16(sb + TILE_BY + so0, B_arr + (size_t)(n0 + r0) * DIM_ + k0 + c80);
        cp16(sb + so1,           A_    + (size_t)(m0 + r1) * DIM_ + k0 + c81);
        cp16(sb + TILE_BY + so1, B_arr + (size_t)(n0 + r1) * DIM_ + k0 + c81);
        CP_COMMIT();
    };

    stage(0, 0);
    stage(1, 1);

    int buf = 0;
    #pragma unroll 1
    for (int kb = 0; kb < NKB; kb++) {
        if (kb + 1 < NKB) CP_WAIT(1); else CP_WAIT(0);
        __syncthreads();

        const uint32_t sb = smb + buf * BUF1_BY;
        #pragma unroll
        for (int ks = 0; ks < 2; ks++) {
            uint32_t ah[2][4], bh[4][4];
            #pragma unroll
            for (int mt = 0; mt < 2; mt++)
                ldm4(ah[mt], sb + aoff[mt] + ks * 32);
            #pragma unroll
            for (int pr = 0; pr < 4; pr++)
                ldm4(bh[pr], sb + boff[pr] + ks * 32 + TILE_BY);
            #pragma unroll
            for (int mt = 0; mt < 2; mt++)
                #pragma unroll
                for (int nt = 0; nt < 8; nt++) {
                    const uint32_t* f = bh[nt >> 1];
                    mma16816(g.acc[mt][nt], ah[mt], (nt & 1) ? f[2] : f[0],
                             (nt & 1) ? f[3] : f[1]);
                }
        }
        __syncthreads();
        if (kb + 2 < NKB) stage(kb + 2, (kb + 2) % 3);
        buf = (buf + 1 == 3) ? 0 : buf + 1;
    }
}

// ---------------------------------------------------------------------------
// Wo GEMM: plain fp32 epilogue into d_out.
// ---------------------------------------------------------------------------
__global__ __launch_bounds__(256) void hmma_gemm1(const __half* __restrict__ A_,
                                                  const __half* __restrict__ B_arr,
                                                  float* __restrict__ C, int Ncols) {
    extern __shared__ __align__(128) __half sm[];
    GemmCtx g;
    const int tid = threadIdx.x, wid = tid >> 5;
    g.lane = tid & 31;
    g.wm = (wid & 3) * 32;
    g.wn = (wid >> 2) * 64;
    g.m0 = blockIdx.y * 128;
    g.n0 = blockIdx.x * 128;

    gemm_mainloop(g, sm, A_, B_arr);

    #pragma unroll
    for (int mt = 0; mt < 2; mt++) {
        const int row = g.m0 + g.wm + mt * 16 + (g.lane >> 2);
        #pragma unroll
        for (int nt = 0; nt < 8; nt++) {
            const int col = g.n0 + g.wn + nt * 8 + (g.lane & 3) * 2;
            float2 lo; lo.x = g.acc[mt][nt][0]; lo.y = g.acc[mt][nt][1];
            float2 hi; hi.x = g.acc[mt][nt][2]; hi.y = g.acc[mt][nt][3];
            *(float2*)&C[(size_t)row * Ncols + col]       = lo;
            *(float2*)&C[(size_t)(row + 8) * Ncols + col] = hi;
        }
    }
}

// ---------------------------------------------------------------------------
// QKV GEMM with fused RMSNorm+RoPE epilogue.
// Tiles x 0-7: Q -> g_qh fp16 (normed, roped, scaled 1/8).
// Tiles 8-9:  K -> g_kvh[.. 0..255] fp16 (normed, roped).
// Tiles 10-11: V -> g_kvh[.. 256..511] fp16 (passthrough).
// ---------------------------------------------------------------------------
__global__ __launch_bounds__(256) void hmma_gemm_qkv(const __half* __restrict__ A_,
                                                     const __half* __restrict__ B_arr,
                                                     const float* __restrict__ gq,
                                                     const float* __restrict__ gk) {
    extern __shared__ __align__(128) __half sm[];
    __shared__ float sg[128];
    const int tid = threadIdx.x, wid = tid >> 5;
    if (tid < 64)            sg[tid]      = gq[tid];
    else if (tid < 128)      sg[tid]      = gk[tid - 64];

    GemmCtx g;
    g.lane = tid & 31;
    g.wm = (wid & 3) * 32;
    g.wn = (wid >> 2) * 64;
    g.m0 = blockIdx.y * 128;
    g.n0 = blockIdx.x * 128;

    gemm_mainloop(g, sm, A_, B_arr);   // contains syncthreads -> sg visible

    const int lane = g.lane;
    const bool isQ = g.n0 < 1024;
    const bool isV = g.n0 >= 1280;
    const float* gg = isQ ? sg : sg + 64;

    float ifr[8];
    if (!isV) {
        #pragma unroll
        for (int nt = 0; nt < 8; nt++)
            ifr[nt] = exp2f((float)(nt * 4 + (lane & 3)) *
                            (-13.287712379549449f / 32.0f));
    }

    #pragma unroll
    for (int mt = 0; mt < 2; mt++)
        #pragma unroll
        for (int rh = 0; rh < 2; rh++) {
            const int row = g.m0 + g.wm + mt * 16 + (lane >> 2) + rh * 8;
            if (!isV) {
                float ss = 0.0f;
                #pragma unroll
                for (int nt = 0; nt < 8; nt++) {
                    float a0 = g.acc[mt][nt][rh * 2];
                    float a1 = g.acc[mt][nt][rh * 2 + 1];
                    ss += a0 * a0 + a1 * a1;
                }
                ss += __shfl_xor_sync(0xffffffffu, ss, 1);
                ss += __shfl_xor_sync(0xffffffffu, ss, 2);
                float rn = rsqrtf(ss * (1.0f / 64.0f) + 1e-6f);
                const float pos = (float)(row & (L_ - 1));
                #pragma unroll
                for (int nt = 0; nt < 8; nt++) {
                    int ch = nt * 8 + (lane & 3) * 2;   // col in head
                    float t1 = g.acc[mt][nt][rh * 2]     * rn * gg[ch];
                    float t2 = g.acc[mt][nt][rh * 2 + 1] * rn * gg[ch + 1];
                    float s, c;
                    sincosf(pos * ifr[nt], &s, &c);
                    float o0 = t1 * c - t2 * s;
                    float o1 = t1 * s + t2 * c;
                    int col = g.n0 + g.wn + ch;
                    if (isQ) {
                        *(uint32_t*)&g_qh[(size_t)row * DIM_ + col] =
                            pack2h(__float2half(o0 * 0.125f),
                                   __float2half(o1 * 0.125f));
                    } else {
                        *(uint32_t*)&g_kvh[(size_t)row * 512 + (col - 1024)] =
                            pack2h(__float2half(o0), __float2half(o1));
                    }
                }
            } else {
                #pragma unroll
                for (int nt = 0; nt < 8; nt++) {
                    int col = g.n0 + g.wn + nt * 8 + (lane & 3) * 2;
                    *(uint32_t*)&g_kvh[(size_t)row * 512 + 256 + (col - 1280)] =
                        pack2h(__float2half(g.acc[mt][nt][rh * 2]),
                               __float2half(g.acc[mt][nt][rh * 2 + 1]));
                }
            }
        }
}

// ---------------------------------------------------------------------------
__global__ __launch_bounds__(256) void cvt16(const float* __restrict__ src,
                                             __half* __restrict__ dst) {
    size_t i = ((size_t)blockIdx.x * 256 + threadIdx.x) * 4;
    float4 v = *(const float4*)(src + i);
    ushort4 H;
    H.x = __half_as_ushort(__float2half(v.x));
    H.y = __half_as_ushort(__float2half(v.y));
    H.z = __half_as_ushort(__float2half(v.z));
    H.w = __half_as_ushort(__float2half(v.w));
    *(ushort4*)(dst + i) = H;
}

// ---------------------------------------------------------------------------
__global__ void wtrans4(const float* __restrict__ wq, const float* __restrict__ wk,
                        const float* __restrict__ wv, const float* __restrict__ wo) {
    const int z = blockIdx.z;
    const float* W;
    __half* T;
    int N;
    if (z == 0)      { W = wq; T = g_wt;               N = 1024; }
    else if (z == 1) { W = wk; T = g_wt + 1024 * DIM_; N = 256;  }
    else if (z == 2) { W = wv; T = g_wt + 1280 * DIM_; N = 256;  }
    else             { W = wo; T = g_wot;              N = 1024; }
    const int n0 = blockIdx.x * 32;
    if (n0 >= N) return;
    const int k0 = blockIdx.y * 32;

    __shared__ float t[32][33];
    const int tx = threadIdx.x, ty = threadIdx.y;
    #pragma unroll
    for (int i = 0; i < 4; i++) {
        int r = ty + i * 8;
        t[r][tx] = W[(size_t)(k0 + r) * N + n0 + tx];
    }
    __syncthreads();
    #pragma unroll
    for (int i = 0; i < 4; i++) {
        int r = ty + i * 8;
        T[(size_t)(n0 + r) * DIM_ + k0 + tx] = __float2half(t[tx][r]);
    }
}

// ---------------------------------------------------------------------------
// HMMA flash attention, fp16 single-term. 512 threads = 16 warps.
// Warp = (head hl 0..3, quarter qq 0..3): 16 q-rows x 64 keys.
// Q pre-scaled fp16 (g_qh); K roped fp16; V fp16 (g_kvh).
// ---------------------------------------------------------------------------
#define AP      72
#define QH_OFF  0                       // 4*64*AP = 18432 halfs
#define KH_OFF  (4*64*AP)               // 18432
#define VH_OFF  (KH_OFF + 64*AP)        // 23040
#define P_OFF   (VH_OFF + 64*AP)        // 27648
#define PW_SZ   (16*AP)                 // 1152 halfs per warp
#define FSMEM   ((P_OFF + 16*PW_SZ)*2)  // 92160 bytes

__global__ __launch_bounds__(512, 1) void fattn_kernel() {
    extern __shared__ __align__(16) __half fsm[];

    const int tid  = threadIdx.x;
    const int w    = tid >> 5;
    const int lane = tid & 31;
    const int t    = blockIdx.x;
    const int bz   = blockIdx.y;
    const int b    = bz >> 2;
    const int hk   = bz & 3;
    const int hl   = w >> 2;            // head within kv group
    const int h    = hk * 4 + hl;
    const int qq   = w & 3;             // 16-row quarter
    const uint32_t smb = smem_u32(fsm);

    // ---- copy Q (4 heads, pre-scaled fp16) into smem ----
    #pragma unroll
    for (int u = 0; u < 4; u++) {
        int idx = tid + (u << 9);           // 0..2047 chunks of 8 halfs
        int hh  = idx >> 9;
        int rem = idx & 511;
        int row = rem >> 3, c8 = (rem & 7) << 3;
        const __half* src = g_qh + (size_t)(b * L_ + t * 64 + row) * DIM_
                          + (hk * 4 + hh) * 64 + c8;
        *(uint4*)(fsm + QH_OFF + hh * 64 * AP + row * AP + c8) =
            *(const uint4*)src;
    }

    float sO[8][4];
    #pragma unroll
    for (int j = 0; j < 8; j++)
        #pragma unroll
        for (int r = 0; r < 4; r++) sO[j][r] = 0.0f;
    float ms[2]   = {-1e30f, -1e30f};
    float ssum[2] = {0.0f, 0.0f};

    const uint32_t pw = P_OFF + w * PW_SZ;

    // per-warp fragment addresses
    uint32_t qoff[4], koff[4], poff[4], voff[4];
    #pragma unroll
    for (int kt = 0; kt < 4; kt++) {
        qoff[kt] = smb + 2 * (QH_OFF + hl * 64 * AP
                   + (qq * 16 + (lane & 15)) * AP
                   + kt * 16 + ((lane >> 4) << 3));
        poff[kt] = smb + 2 * (pw + (lane & 15) * AP
                   + kt * 16 + ((lane >> 4) << 3));
    }
    #pragma unroll
    for (int pr = 0; pr < 4; pr++) {
        koff[pr] = smb + 2 * (KH_OFF
                   + (pr * 16 + (lane & 7) + ((lane >> 4) & 1) * 8) * AP
                   + (((lane >> 3) & 1) << 3));
        voff[pr] = smb + 2 * (VH_OFF
                   + ((lane & 7) + ((lane >> 3) & 1) * 8) * AP
                   + pr * 16 + (((lane >> 4) & 1) << 3));
    }

    auto do_chunk = [&](int kb, bool partial) {
        __syncthreads();
        // ---- copy K/V fp16 chunk to smem (512 threads, 1 pass) ----
        {
            int row = tid >> 3, h8 = (tid & 7) << 3;
            const __half* base = g_kvh + (size_t)(b * L_ + kb + row) * 512
                               + hk * 64 + h8;
            *(uint4*)(fsm + KH_OFF + row * AP + h8) = *(const uint4*)base;
            *(uint4*)(fsm + VH_OFF + row * AP + h8) = *(const uint4*)(base + 256);
        }
        __syncthreads();

        // ---- S = Q K^T ----
        float sS[8][4];
        #pragma unroll
        for (int j = 0; j < 8; j++)
            #pragma unroll
            for (int r = 0; r < 4; r++) sS[j][r] = 0.0f;

        #pragma unroll
        for (int kt = 0; kt < 4; kt++) {
            uint32_t ah[4], bh[4][4];
            ldm4(ah, qoff[kt]);
            #pragma unroll
            for (int pr = 0; pr < 4; pr++)
                ldm4(bh[pr], koff[pr] + kt * 32);
            #pragma unroll
            for (int nt = 0; nt < 8; nt++) {
                const uint32_t* f = bh[nt >> 1];
                mma16816(sS[nt], ah, (nt & 1) ? f[2] : f[0],
                         (nt & 1) ? f[3] : f[1]);
            }
        }

        if (partial) {
            #pragma unroll
            for (int rh = 0; rh < 2; rh++) {
                int iq = t * 64 + qq * 16 + (lane >> 2) + rh * 8;
                #pragma unroll
                for (int nt = 0; nt < 8; nt++)
                    #pragma unroll
                    for (int c = 0; c < 2; c++) {
                        int j = kb + nt * 8 + (lane & 3) * 2 + c;
                        bool valid = (j <= iq) && ((j >= iq - 256) || (j < 64));
                        if (!valid) sS[nt][rh * 2 + c] = -INFINITY;
                    }
            }
        }

        // ---- online softmax ----
        #pragma unroll
        for (int rh = 0; rh < 2; rh++) {
            float rmax = -INFINITY;
            #pragma unroll
            for (int nt = 0; nt < 8; nt++)
                rmax = fmaxf(rmax, fmaxf(sS[nt][rh*2], sS[nt][rh*2+1]));
            rmax = fmaxf(rmax, __shfl_xor_sync(0xffffffffu, rmax, 1));
            rmax = fmaxf(rmax, __shfl_xor_sync(0xffffffffu, rmax, 2));
            float mn = fmaxf(ms[rh], rmax);
            float corr = __expf(ms[rh] - mn);
            float rs = 0.0f;
            #pragma unroll
            for (int nt = 0; nt < 8; nt++) {
                float e0 = __expf(sS[nt][rh*2]     - mn);
                float e1 = __expf(sS[nt][rh*2 + 1] - mn);
                sS[nt][rh*2] = e0; sS[nt][rh*2+1] = e1;
                sO[nt][rh*2]   *= corr;
                sO[nt][rh*2+1] *= corr;
                rs += e0 + e1;
            }
            rs += __shfl_xor_sync(0xffffffffu, rs, 1);
            rs += __shfl_xor_sync(0xffffffffu, rs, 2);
            ssum[rh] = ssum[rh] * corr + rs;
            ms[rh] = mn;
        }

        // ---- P (fp16) x V ----
        #pragma unroll
        for (int rh = 0; rh < 2; rh++)
            #pragma unroll
            for (int nt = 0; nt < 8; nt++) {
                uint32_t pk = pack2h(__float2half(sS[nt][rh*2]),
                                     __float2half(sS[nt][rh*2+1]));
                uint32_t off = pw + ((lane >> 2) + rh * 8) * AP
                             + nt * 8 + (lane & 3) * 2;
                *(uint32_t*)((char*)fsm + 2 * off) = pk;
            }
        __syncwarp();
        #pragma unroll
        for (int kt = 0; kt < 4; kt++) {
            uint32_t ap[4], vh[4][4];
            ldm4(ap, poff[kt]);
            #pragma unroll
            for (int pr = 0; pr < 4; pr++)
                ldm4t(vh[pr], voff[pr] + kt * 16 * AP * 2);
            #pragma unroll
            for (int nt = 0; nt < 8; nt++) {
                const uint32_t* f = vh[nt >> 1];
                mma16816(sO[nt], ap, (nt & 1) ? f[2] : f[0],
                         (nt & 1) ? f[3] : f[1]);
            }
        }
        __syncwarp();
    };

    if (t > 4) do_chunk(0, false);
    int c0 = t - 4; if (c0 < 0) c0 = 0;
    for (int cc = c0; cc <= t; cc++) {
        bool partial = (cc == t) || (t >= 5 && cc == t - 4);
        do_chunk(cc * 64, partial);
    }

    // ---- epilogue: normalize, write single fp16 ----
    #pragma unroll
    for (int rh = 0; rh < 2; rh++) {
        float inv = 1.0f / ssum[rh];
        int tok = b * L_ + t * 64 + qq * 16 + (lane >> 2) + rh * 8;
        #pragma unroll
        for (int nt = 0; nt < 8; nt++) {
            float v0 = sO[nt][rh*2]     * inv;
            float v1 = sO[nt][rh*2 + 1] * inv;
            size_t o = (size_t)tok * DIM_ + h * 64 + nt * 8 + (lane & 3) * 2;
            *(uint32_t*)&g_ao[o] = pack2h(__float2half(v0), __float2half(v1));
        }
    }
}

// ---------------------------------------------------------------------------
extern "C" void kernel_launch(void* const* d_in, const int* in_sizes, int n_in,
                              void* d_out, int out_size) {
    const float* x  = (const float*)d_in[0];
    const float* wq = (const float*)d_in[1];
    const float* wk = (const float*)d_in[2];
    const float* wv = (const float*)d_in[3];
    const float* wo = (const float*)d_in[4];
    const float* gq = (const float*)d_in[5];
    const float* gk = (const float*)d_in[6];

    __half *xh, *ao, *wt, *wot;
    cudaGetSymbolAddress((void**)&xh,  g_xh);
    cudaGetSymbolAddress((void**)&ao,  g_ao);
    cudaGetSymbolAddress((void**)&wt,  g_wt);
    cudaGetSymbolAddress((void**)&wot, g_wot);

    cudaFuncSetAttribute(hmma_gemm1, cudaFuncAttributeMaxDynamicSharedMemorySize,
                         GSMEM1);
    cudaFuncSetAttribute(hmma_gemm_qkv, cudaFuncAttributeMaxDynamicSharedMemorySize,
                         GSMEM1);
    cudaFuncSetAttribute(fattn_kernel, cudaFuncAttributeMaxDynamicSharedMemorySize,
                         FSMEM);

    // preps: input convert + fused weight transposes
    cvt16<<<NTOK * DIM_ / 1024, 256>>>(x, xh);
    wtrans4<<<dim3(32, 32, 4), dim3(32, 8)>>>(wq, wk, wv, wo);

    // fused Q|K|V projection + RMSNorm + RoPE + fp16 Q/K/V emission
    hmma_gemm_qkv<<<dim3(12, NTOK / 128), 256, GSMEM1>>>(xh, wt, gq, gk);

    // flash attention (fp16 in/out)
    fattn_kernel<<<dim3(32, 8), 512, FSMEM>>>();

    // output projection
    hmma_gemm1<<<dim3(DIM_ / 128, NTOK / 128), 256, GSMEM1>>>(ao, wot,
                                                              (float*)d_out, DIM_);
}